// round 10
// baseline (speedup 1.0000x reference)
#include <cuda_runtime.h>
#include <cuda_bf16.h>

// Problem shape (fixed by reference setup_inputs)
#define NB 64
#define LL 512
#define DD 840
#define NVEC (DD / 4)     // 210 float4 per row
#define NWARPS (LL / 32)
#define NBINS 1024        // noise in [0,1) -> float bits < 2^30 -> bits>>20 < 1024
#define ROWS_PER_BLK 16   // gather: warp-per-row, 16 warps/block

// Scratch (no device allocation allowed anywhere)
__device__ int g_perm[NB * LL];   // perm[n*LL+j] = source row for output row j
__device__ int g_lenkeep[NB];

// ---------------------------------------------------------------------------
// Kernel 1: fused selection (O(L) radix-threshold) + compaction + masks.
// One block per sample, 512 threads.
//   1. 1024-bin histogram of candidate noise bits (bits>>20)
//   2. block scan of bins -> find bin b holding the len_keep-th smallest
//   3. bins < b kept; bin == b resolved by exact stable in-bin rank
//      (expected in-bin population < 1, worst case still exact)
//   4. inclusive scan of keep flags -> order-preserving compaction -> perm
// ---------------------------------------------------------------------------
__global__ void select_kernel(const float* __restrict__ noise,
                              const int* __restrict__ lengths,
                              float* __restrict__ out) {
    const int n    = blockIdx.x;
    const int i    = threadIdx.x;
    const int lane = i & 31;
    const int warp = i >> 5;

    __shared__ unsigned int bits[LL];
    __shared__ int hist[NBINS];
    __shared__ int wsum[NWARPS];
    __shared__ int sh_bin, sh_base;

    int length = lengths[n];                       // overlaps smem fill
    const unsigned int b32 = __float_as_uint(__ldg(&noise[n * LL + i]));
    bits[i] = b32;
    hist[2 * i]     = 0;
    hist[2 * i + 1] = 0;

    length = max(16, min(LL, length));
    const int last     = length - 1;               // candidates: i < last
    const int len_keep = (int)((float)length * 0.5f);   // f32 mul+trunc, matches ref
    const int cand     = (i < last);
    const int mybin    = (int)(b32 >> 20);
    __syncthreads();

    if (cand) atomicAdd(&hist[mybin], 1);
    __syncthreads();

    // Block scan over 1024 bins: each thread owns bins {2i, 2i+1}.
    const int c0 = hist[2 * i];
    const int c1 = hist[2 * i + 1];
    int ws = c0 + c1;
    #pragma unroll
    for (int off = 1; off < 32; off <<= 1) {
        int v = __shfl_up_sync(0xFFFFFFFFu, ws, off);
        if (lane >= off) ws += v;
    }
    if (lane == 31) wsum[warp] = ws;
    __syncthreads();
    if (warp == 0 && lane < NWARPS) {
        int v = wsum[lane];
        #pragma unroll
        for (int off = 1; off < NWARPS; off <<= 1) {
            int u = __shfl_up_sync(0xFFFFu, v, off);
            if (lane >= off) v += u;
        }
        wsum[lane] = v;
    }
    __syncthreads();
    const int incl_pair = ws + (warp ? wsum[warp - 1] : 0);
    const int pre       = incl_pair - c0 - c1;     // candidates in bins < 2i

    // Locate threshold bin: smallest b with cum(<=b) >= len_keep. Exactly one
    // (thread, sub-bin) pair matches — the two ranges are disjoint.
    if (pre < len_keep && len_keep <= pre + c0) {
        sh_bin = 2 * i;     sh_base = pre;
    } else if (pre + c0 < len_keep && len_keep <= incl_pair) {
        sh_bin = 2 * i + 1; sh_base = pre + c0;
    }
    __syncthreads();
    const int tbin = sh_bin;    // threshold bin
    const int base = sh_base;   // # kept from bins < tbin

    // keep decision; exact stable rank only for the (rare) threads in tbin.
    int keep = 0;
    if (cand) {
        if (mybin < tbin) {
            keep = 1;
        } else if (mybin == tbin) {
            int r = 0;
            for (int j = 0; j < last; ++j) {
                const unsigned int wb = bits[j];
                r += ((int)(wb >> 20) == tbin) &
                     ((wb < b32) | ((wb == b32) & (j < i)));   // stable compare
            }
            keep = (base + r < len_keep);
        }
    }

    // Inclusive scan of keep flags -> order-preserving compaction
    int ks = keep;
    #pragma unroll
    for (int off = 1; off < 32; off <<= 1) {
        int v = __shfl_up_sync(0xFFFFFFFFu, ks, off);
        if (lane >= off) ks += v;
    }
    if (lane == 31) wsum[warp] = ks;
    __syncthreads();
    if (warp == 0 && lane < NWARPS) {
        int v = wsum[lane];
        #pragma unroll
        for (int off = 1; off < NWARPS; off <<= 1) {
            int u = __shfl_up_sync(0xFFFFu, v, off);
            if (lane >= off) v += u;
        }
        wsum[lane] = v;
    }
    __syncthreads();
    const int incl = ks + (warp ? wsum[warp - 1] : 0);

    if (keep) g_perm[n * LL + (incl - 1)] = i;
    if (i == 0) g_lenkeep[n] = len_keep;

    // Mask outputs (packed after masked_x in d_out, return order)
    const long long MX = (long long)NB * LL * DD;
    const float m = (i < len_keep) ? 1.0f : 0.0f;
    out[MX + (long long)n * LL + i]            = m;           // masked_attention_mask
    out[MX + (long long)(NB + n) * LL + i]     = 1.0f - m;    // invert
    out[MX + (long long)(2 * NB + n) * LL + i] =
        (!keep && i < length) ? 1.0f : 0.0f;                  // removed_mask
}

// ---------------------------------------------------------------------------
// Kernel 2: row gather, warp-per-row, 16 rows per block.
// Each thread batches 7 independent float4 loads (MLP=7) then 7 stores.
//   j <  len_keep : copy x[n, perm[j], :]
//   j >= len_keep : zero (mask == 0)
// ---------------------------------------------------------------------------
__global__ void gather_kernel(const float* __restrict__ x,
                              float* __restrict__ out) {
    const int lane = threadIdx.x & 31;
    const int warp = threadIdx.x >> 5;
    const int row  = blockIdx.x * ROWS_PER_BLK + warp;   // 0..NB*LL-1
    const int n = row >> 9;          // LL = 512
    const int j = row & (LL - 1);

    float4* __restrict__ orow = (float4*)(out + (long long)row * DD);
    const int lk = g_lenkeep[n];

    if (j < lk) {
        const int src = g_perm[n * LL + j];
        const float4* __restrict__ xrow =
            (const float4*)(x + ((long long)(n * LL + src)) * DD);
        float4 v[7];
        #pragma unroll
        for (int k = 0; k < 6; ++k) v[k] = __ldg(&xrow[lane + 32 * k]);
        if (lane < NVEC - 192) v[6] = __ldg(&xrow[lane + 192]);   // 210-192=18 lanes
        #pragma unroll
        for (int k = 0; k < 6; ++k) orow[lane + 32 * k] = v[k];
        if (lane < NVEC - 192) orow[lane + 192] = v[6];
    } else {
        const float4 z = make_float4(0.f, 0.f, 0.f, 0.f);
        #pragma unroll
        for (int k = 0; k < 6; ++k) orow[lane + 32 * k] = z;
        if (lane < NVEC - 192) orow[lane + 192] = z;
    }
}

extern "C" void kernel_launch(void* const* d_in, const int* in_sizes, int n_in,
                              void* d_out, int out_size) {
    const float* x       = (const float*)d_in[0];   // [64, 512, 840] f32
    const float* noise   = (const float*)d_in[1];   // [64, 512] f32
    const int*   lengths = (const int*)d_in[2];     // [64] i32
    float* out = (float*)d_out;

    select_kernel<<<NB, LL>>>(noise, lengths, out);
    gather_kernel<<<(NB * LL) / ROWS_PER_BLK, ROWS_PER_BLK * 32>>>(x, out);
}

// round 11
// speedup vs baseline: 1.4486x; 1.4486x over previous
#include <cuda_runtime.h>
#include <cuda_bf16.h>

// Problem shape (fixed by reference setup_inputs)
#define NB 64
#define LL 512
#define DD 840
#define NVEC (DD / 4)     // 210 float4 per row
#define NWARPS (LL / 32)
#define NBINS 1024        // uniform value bins: (int)(noise * 1024), noise in [0,1)
#define ROWS_PER_BLK 16   // gather: warp-per-row, 16 warps/block

// Scratch (no device allocation allowed anywhere)
__device__ int g_perm[NB * LL];   // perm[n*LL+j] = source row for output row j
__device__ int g_lenkeep[NB];

// ---------------------------------------------------------------------------
// Kernel 1: fused selection (O(L) uniform-bin threshold) + compaction + masks.
// One block per sample, 512 threads.
//   1. 1024 UNIFORM value bins (noise*1024) — E[per-bin] ~ 0.5 candidates.
//      (bits>>20 binning was the R10 bug: IEEE bins are logarithmic, so the
//       median-quantile threshold bin held ~32 elements -> O(L^2) fallback.)
//   2. block scan of bins -> bin b holding the len_keep-th smallest
//   3. bins < b kept; bin == b resolved exactly against a tiny smem list of
//      the bin's members (stable (bits,index) compare), O(m^2), m ~ 1-3.
//   4. inclusive scan of keep flags -> order-preserving compaction -> perm
// ---------------------------------------------------------------------------
__global__ void select_kernel(const float* __restrict__ noise,
                              const int* __restrict__ lengths,
                              float* __restrict__ out) {
    const int n    = blockIdx.x;
    const int i    = threadIdx.x;
    const int lane = i & 31;
    const int warp = i >> 5;

    __shared__ int hist[NBINS];
    __shared__ unsigned long long tlist[LL];   // threshold-bin members (worst case all)
    __shared__ int wsum[NWARPS];
    __shared__ int sh_bin, sh_base, sh_cnt;

    int length = lengths[n];                       // overlaps the loads below
    const float v = __ldg(&noise[n * LL + i]);
    const unsigned int b32 = __float_as_uint(v);
    hist[2 * i]     = 0;
    hist[2 * i + 1] = 0;
    if (i == 0) sh_cnt = 0;

    length = max(16, min(LL, length));
    const int last     = length - 1;               // candidates: i < last
    const int len_keep = (int)((float)length * 0.5f);   // f32 mul+trunc, matches ref
    const int cand     = (i < last);
    const int mybin    = min(NBINS - 1, (int)(v * (float)NBINS));  // uniform, monotone
    __syncthreads();

    if (cand) atomicAdd(&hist[mybin], 1);
    __syncthreads();

    // Block scan over 1024 bins: each thread owns bins {2i, 2i+1}.
    const int c0 = hist[2 * i];
    const int c1 = hist[2 * i + 1];
    int ws = c0 + c1;
    #pragma unroll
    for (int off = 1; off < 32; off <<= 1) {
        int u = __shfl_up_sync(0xFFFFFFFFu, ws, off);
        if (lane >= off) ws += u;
    }
    if (lane == 31) wsum[warp] = ws;
    __syncthreads();
    if (warp == 0 && lane < NWARPS) {
        int s = wsum[lane];
        #pragma unroll
        for (int off = 1; off < NWARPS; off <<= 1) {
            int u = __shfl_up_sync(0xFFFFu, s, off);
            if (lane >= off) s += u;
        }
        wsum[lane] = s;
    }
    __syncthreads();
    const int incl_pair = ws + (warp ? wsum[warp - 1] : 0);
    const int pre       = incl_pair - c0 - c1;     // candidates in bins < 2i

    // Threshold bin: smallest b with cum(<=b) >= len_keep. Exactly one
    // (thread, sub-bin) pair matches — the two ranges are disjoint.
    if (pre < len_keep && len_keep <= pre + c0) {
        sh_bin = 2 * i;     sh_base = pre;
    } else if (pre + c0 < len_keep && len_keep <= incl_pair) {
        sh_bin = 2 * i + 1; sh_base = pre + c0;
    }
    __syncthreads();
    const int tbin = sh_bin;    // threshold bin
    const int base = sh_base;   // # kept from bins < tbin

    // Collect threshold-bin members into a tiny list (key = bits<<9 | index,
    // stable sort order since noise >= 0 -> bits are value-monotone).
    const unsigned long long mykey = ((unsigned long long)b32 << 9) | (unsigned)i;
    int inbin = cand && (mybin == tbin);
    if (inbin) tlist[atomicAdd(&sh_cnt, 1)] = mykey;
    __syncthreads();
    const int m = sh_cnt;

    // keep decision; exact stable rank only within the (small) list.
    int keep = 0;
    if (cand) {
        if (mybin < tbin) {
            keep = 1;
        } else if (inbin) {
            int r = 0;
            for (int t = 0; t < m; ++t) r += (tlist[t] < mykey);
            keep = (base + r < len_keep);
        }
    }

    // Inclusive scan of keep flags -> order-preserving compaction
    int ks = keep;
    #pragma unroll
    for (int off = 1; off < 32; off <<= 1) {
        int u = __shfl_up_sync(0xFFFFFFFFu, ks, off);
        if (lane >= off) ks += u;
    }
    if (lane == 31) wsum[warp] = ks;
    __syncthreads();
    if (warp == 0 && lane < NWARPS) {
        int s = wsum[lane];
        #pragma unroll
        for (int off = 1; off < NWARPS; off <<= 1) {
            int u = __shfl_up_sync(0xFFFFu, s, off);
            if (lane >= off) s += u;
        }
        wsum[lane] = s;
    }
    __syncthreads();
    const int incl = ks + (warp ? wsum[warp - 1] : 0);

    if (keep) g_perm[n * LL + (incl - 1)] = i;
    if (i == 0) g_lenkeep[n] = len_keep;

    // Mask outputs (packed after masked_x in d_out, return order)
    const long long MX = (long long)NB * LL * DD;
    const float mval = (i < len_keep) ? 1.0f : 0.0f;
    out[MX + (long long)n * LL + i]            = mval;         // masked_attention_mask
    out[MX + (long long)(NB + n) * LL + i]     = 1.0f - mval;  // invert
    out[MX + (long long)(2 * NB + n) * LL + i] =
        (!keep && i < length) ? 1.0f : 0.0f;                   // removed_mask
}

// ---------------------------------------------------------------------------
// Kernel 2: row gather, warp-per-row, 16 rows per block. (unchanged from R10)
// Each thread batches 7 independent float4 loads (MLP=7) then 7 stores.
//   j <  len_keep : copy x[n, perm[j], :]
//   j >= len_keep : zero (mask == 0)
// ---------------------------------------------------------------------------
__global__ void gather_kernel(const float* __restrict__ x,
                              float* __restrict__ out) {
    const int lane = threadIdx.x & 31;
    const int warp = threadIdx.x >> 5;
    const int row  = blockIdx.x * ROWS_PER_BLK + warp;   // 0..NB*LL-1
    const int n = row >> 9;          // LL = 512
    const int j = row & (LL - 1);

    float4* __restrict__ orow = (float4*)(out + (long long)row * DD);
    const int lk = g_lenkeep[n];

    if (j < lk) {
        const int src = g_perm[n * LL + j];
        const float4* __restrict__ xrow =
            (const float4*)(x + ((long long)(n * LL + src)) * DD);
        float4 v[7];
        #pragma unroll
        for (int k = 0; k < 6; ++k) v[k] = __ldg(&xrow[lane + 32 * k]);
        if (lane < NVEC - 192) v[6] = __ldg(&xrow[lane + 192]);   // 210-192=18 lanes
        #pragma unroll
        for (int k = 0; k < 6; ++k) orow[lane + 32 * k] = v[k];
        if (lane < NVEC - 192) orow[lane + 192] = v[6];
    } else {
        const float4 z = make_float4(0.f, 0.f, 0.f, 0.f);
        #pragma unroll
        for (int k = 0; k < 6; ++k) orow[lane + 32 * k] = z;
        if (lane < NVEC - 192) orow[lane + 192] = z;
    }
}

extern "C" void kernel_launch(void* const* d_in, const int* in_sizes, int n_in,
                              void* d_out, int out_size) {
    const float* x       = (const float*)d_in[0];   // [64, 512, 840] f32
    const float* noise   = (const float*)d_in[1];   // [64, 512] f32
    const int*   lengths = (const int*)d_in[2];     // [64] i32
    float* out = (float*)d_out;

    select_kernel<<<NB, LL>>>(noise, lengths, out);
    gather_kernel<<<(NB * LL) / ROWS_PER_BLK, ROWS_PER_BLK * 32>>>(x, out);
}

// round 12
// speedup vs baseline: 1.5354x; 1.0600x over previous
#include <cuda_runtime.h>
#include <cuda_bf16.h>

// Problem shape (fixed by reference setup_inputs)
#define NB 64
#define LL 512
#define DD 840
#define NVEC (DD / 4)     // 210 float4 per row
#define NWARPS (LL / 32)
#define NBINS 1024        // uniform value bins: (int)(noise * 1024), noise in [0,1)
#define ROWS_PER_BLK 16   // warp-per-row, 16 warps/block
#define HALF (LL / 2)     // 256: len_keep <= 256 always -> rows j>=256 are always zero

// Scratch (no device allocation allowed anywhere)
__device__ int g_perm[NB * LL];   // perm[n*LL+j] = source row for output row j
__device__ int g_lenkeep[NB];

// ---------------------------------------------------------------------------
// Kernel A: blocks [0,64)  -> fused selection (unchanged from R11)
//           blocks [64, ..) -> zero the always-zero back half (j >= 256)
// The 55 MB of unconditional zero stores hides the select latency entirely.
// ---------------------------------------------------------------------------
__global__ void select_zero_kernel(const float* __restrict__ noise,
                                   const int* __restrict__ lengths,
                                   float* __restrict__ out) {
    if (blockIdx.x >= NB) {
        // ---- zero back-half rows: 16384 rows, warp-per-row ----
        const int lane = threadIdx.x & 31;
        const int warp = threadIdx.x >> 5;
        const int idx  = (blockIdx.x - NB) * ROWS_PER_BLK + warp;  // 0..16383
        const int n = idx >> 8;                 // 256 rows per sample here
        const int j = HALF + (idx & (HALF - 1));
        float4* __restrict__ orow = (float4*)(out + ((long long)(n * LL + j)) * DD);
        const float4 z = make_float4(0.f, 0.f, 0.f, 0.f);
        #pragma unroll
        for (int k = 0; k < 6; ++k) orow[lane + 32 * k] = z;
        if (lane < NVEC - 192) orow[lane + 192] = z;
        return;
    }

    // ---- selection: one block per sample, 512 threads (identical to R11) ----
    const int n    = blockIdx.x;
    const int i    = threadIdx.x;
    const int lane = i & 31;
    const int warp = i >> 5;

    __shared__ int hist[NBINS];
    __shared__ unsigned long long tlist[LL];
    __shared__ int wsum[NWARPS];
    __shared__ int sh_bin, sh_base, sh_cnt;

    int length = lengths[n];
    const float v = __ldg(&noise[n * LL + i]);
    const unsigned int b32 = __float_as_uint(v);
    hist[2 * i]     = 0;
    hist[2 * i + 1] = 0;
    if (i == 0) sh_cnt = 0;

    length = max(16, min(LL, length));
    const int last     = length - 1;                    // candidates: i < last
    const int len_keep = (int)((float)length * 0.5f);   // f32 mul+trunc, matches ref
    const int cand     = (i < last);
    const int mybin    = min(NBINS - 1, (int)(v * (float)NBINS));  // uniform, monotone
    __syncthreads();

    if (cand) atomicAdd(&hist[mybin], 1);
    __syncthreads();

    // Block scan over 1024 bins: each thread owns bins {2i, 2i+1}.
    const int c0 = hist[2 * i];
    const int c1 = hist[2 * i + 1];
    int ws = c0 + c1;
    #pragma unroll
    for (int off = 1; off < 32; off <<= 1) {
        int u = __shfl_up_sync(0xFFFFFFFFu, ws, off);
        if (lane >= off) ws += u;
    }
    if (lane == 31) wsum[warp] = ws;
    __syncthreads();
    if (warp == 0 && lane < NWARPS) {
        int s = wsum[lane];
        #pragma unroll
        for (int off = 1; off < NWARPS; off <<= 1) {
            int u = __shfl_up_sync(0xFFFFu, s, off);
            if (lane >= off) s += u;
        }
        wsum[lane] = s;
    }
    __syncthreads();
    const int incl_pair = ws + (warp ? wsum[warp - 1] : 0);
    const int pre       = incl_pair - c0 - c1;

    if (pre < len_keep && len_keep <= pre + c0) {
        sh_bin = 2 * i;     sh_base = pre;
    } else if (pre + c0 < len_keep && len_keep <= incl_pair) {
        sh_bin = 2 * i + 1; sh_base = pre + c0;
    }
    __syncthreads();
    const int tbin = sh_bin;
    const int base = sh_base;

    const unsigned long long mykey = ((unsigned long long)b32 << 9) | (unsigned)i;
    int inbin = cand && (mybin == tbin);
    if (inbin) tlist[atomicAdd(&sh_cnt, 1)] = mykey;
    __syncthreads();
    const int m = sh_cnt;

    int keep = 0;
    if (cand) {
        if (mybin < tbin) {
            keep = 1;
        } else if (inbin) {
            int r = 0;
            for (int t = 0; t < m; ++t) r += (tlist[t] < mykey);
            keep = (base + r < len_keep);
        }
    }

    // Inclusive scan of keep flags -> order-preserving compaction
    int ks = keep;
    #pragma unroll
    for (int off = 1; off < 32; off <<= 1) {
        int u = __shfl_up_sync(0xFFFFFFFFu, ks, off);
        if (lane >= off) ks += u;
    }
    if (lane == 31) wsum[warp] = ks;
    __syncthreads();
    if (warp == 0 && lane < NWARPS) {
        int s = wsum[lane];
        #pragma unroll
        for (int off = 1; off < NWARPS; off <<= 1) {
            int u = __shfl_up_sync(0xFFFFu, s, off);
            if (lane >= off) s += u;
        }
        wsum[lane] = s;
    }
    __syncthreads();
    const int incl = ks + (warp ? wsum[warp - 1] : 0);

    if (keep) g_perm[n * LL + (incl - 1)] = i;
    if (i == 0) g_lenkeep[n] = len_keep;

    // Mask outputs (packed after masked_x in d_out, return order)
    const long long MX = (long long)NB * LL * DD;
    const float mval = (i < len_keep) ? 1.0f : 0.0f;
    out[MX + (long long)n * LL + i]            = mval;         // masked_attention_mask
    out[MX + (long long)(NB + n) * LL + i]     = 1.0f - mval;  // invert
    out[MX + (long long)(2 * NB + n) * LL + i] =
        (!keep && i < length) ? 1.0f : 0.0f;                   // removed_mask
}

// ---------------------------------------------------------------------------
// Kernel B: gather the FRONT half only (j < 256), warp-per-row, MLP=7.
//   j <  len_keep : copy x[n, perm[j], :]
//   j >= len_keep : zero
// ---------------------------------------------------------------------------
__global__ void gather_kernel(const float* __restrict__ x,
                              float* __restrict__ out) {
    const int lane = threadIdx.x & 31;
    const int warp = threadIdx.x >> 5;
    const int idx  = blockIdx.x * ROWS_PER_BLK + warp;   // 0..16383
    const int n = idx >> 8;               // 256 front rows per sample
    const int j = idx & (HALF - 1);

    float4* __restrict__ orow = (float4*)(out + ((long long)(n * LL + j)) * DD);
    const int lk = g_lenkeep[n];

    if (j < lk) {
        const int src = g_perm[n * LL + j];
        const float4* __restrict__ xrow =
            (const float4*)(x + ((long long)(n * LL + src)) * DD);
        float4 v[7];
        #pragma unroll
        for (int k = 0; k < 6; ++k) v[k] = __ldg(&xrow[lane + 32 * k]);
        if (lane < NVEC - 192) v[6] = __ldg(&xrow[lane + 192]);   // 210-192=18 lanes
        #pragma unroll
        for (int k = 0; k < 6; ++k) orow[lane + 32 * k] = v[k];
        if (lane < NVEC - 192) orow[lane + 192] = v[6];
    } else {
        const float4 z = make_float4(0.f, 0.f, 0.f, 0.f);
        #pragma unroll
        for (int k = 0; k < 6; ++k) orow[lane + 32 * k] = z;
        if (lane < NVEC - 192) orow[lane + 192] = z;
    }
}

extern "C" void kernel_launch(void* const* d_in, const int* in_sizes, int n_in,
                              void* d_out, int out_size) {
    const float* x       = (const float*)d_in[0];   // [64, 512, 840] f32
    const float* noise   = (const float*)d_in[1];   // [64, 512] f32
    const int*   lengths = (const int*)d_in[2];     // [64] i32
    float* out = (float*)d_out;

    // A: 64 select blocks + 1024 zero blocks (16384 back-half rows)
    select_zero_kernel<<<NB + (NB * HALF) / ROWS_PER_BLK, LL>>>(noise, lengths, out);
    // B: 1024 blocks covering the 16384 front-half rows
    gather_kernel<<<(NB * HALF) / ROWS_PER_BLK, ROWS_PER_BLK * 32>>>(x, out);
}